// round 1
// baseline (speedup 1.0000x reference)
#include <cuda_runtime.h>
#include <cuda_bf16.h>

// Batched Kalman update: B=262144, DX=8, DZ=4.
// Inputs (metadata order): x [B,8,1] f32, z [B,4,1] f32, P [B,8,8] f32,
//                          H [4,8] f32, R [4,4] f32.
// Output: [B, 9, 8] f32 = concat(x_new^T (1x8), P_new (8x8)).
//
// One thread per batch. P/S symmetry exploited; S^{-1} applied via 4x4
// Cholesky solves (S = H P H^T + R is SPD, eigenvalues >= 1).

#define BT 256

__global__ void __launch_bounds__(BT) kalman_kernel(
    const float4* __restrict__ x4,
    const float4* __restrict__ z4,
    const float4* __restrict__ P4,
    const float*  __restrict__ Hg,
    const float*  __restrict__ Rg,
    float4*       __restrict__ out4,
    int nb)
{
    __shared__ float Hs[32];
    __shared__ float Rs[16];
    const int tid = threadIdx.x;
    if (tid < 32) Hs[tid] = Hg[tid];
    if (tid < 16) Rs[tid] = Rg[tid];
    __syncthreads();

    const int b = blockIdx.x * BT + tid;
    if (b >= nb) return;

    // ---- Load P [8][8] (16 float4, coalesced at sector granularity) ----
    float p[8][8];
    const float4* Pb = P4 + (size_t)b * 16;
    #pragma unroll
    for (int i = 0; i < 8; i++) {
        float4 a = Pb[i * 2];
        float4 c = Pb[i * 2 + 1];
        p[i][0] = a.x; p[i][1] = a.y; p[i][2] = a.z; p[i][3] = a.w;
        p[i][4] = c.x; p[i][5] = c.y; p[i][6] = c.z; p[i][7] = c.w;
    }

    // ---- Load x [8], z [4] ----
    float xr[8];
    {
        float4 a = x4[(size_t)b * 2];
        float4 c = x4[(size_t)b * 2 + 1];
        xr[0] = a.x; xr[1] = a.y; xr[2] = a.z; xr[3] = a.w;
        xr[4] = c.x; xr[5] = c.y; xr[6] = c.z; xr[7] = c.w;
    }
    float4 zz = z4[b];
    float y0 = zz.x, y1 = zz.y, y2 = zz.z, y3 = zz.w;

    // ---- PHT = P H^T  [8][4]; fold y = z - H x into same k-loop ----
    float PHT[8][4];
    #pragma unroll
    for (int i = 0; i < 8; i++)
        #pragma unroll
        for (int zc = 0; zc < 4; zc++) PHT[i][zc] = 0.f;

    #pragma unroll
    for (int k = 0; k < 8; k++) {
        float h0 = Hs[k], h1 = Hs[8 + k], h2 = Hs[16 + k], h3 = Hs[24 + k];
        y0 -= h0 * xr[k]; y1 -= h1 * xr[k]; y2 -= h2 * xr[k]; y3 -= h3 * xr[k];
        #pragma unroll
        for (int i = 0; i < 8; i++) {
            float pik = p[i][k];
            PHT[i][0] += pik * h0;
            PHT[i][1] += pik * h1;
            PHT[i][2] += pik * h2;
            PHT[i][3] += pik * h3;
        }
    }

    // ---- S = H * PHT + R  (symmetric 4x4, upper triangle) ----
    float S00 = 0.f, S01 = 0.f, S02 = 0.f, S03 = 0.f;
    float S11 = 0.f, S12 = 0.f, S13 = 0.f;
    float S22 = 0.f, S23 = 0.f, S33 = 0.f;
    #pragma unroll
    for (int i = 0; i < 8; i++) {
        float h0 = Hs[i], h1 = Hs[8 + i], h2 = Hs[16 + i], h3 = Hs[24 + i];
        float q0 = PHT[i][0], q1 = PHT[i][1], q2 = PHT[i][2], q3 = PHT[i][3];
        S00 += h0 * q0; S01 += h0 * q1; S02 += h0 * q2; S03 += h0 * q3;
        S11 += h1 * q1; S12 += h1 * q2; S13 += h1 * q3;
        S22 += h2 * q2; S23 += h2 * q3;
        S33 += h3 * q3;
    }
    S00 += Rs[0];  S01 += Rs[1];  S02 += Rs[2];  S03 += Rs[3];
    S11 += Rs[5];  S12 += Rs[6];  S13 += Rs[7];
    S22 += Rs[10]; S23 += Rs[11]; S33 += Rs[15];

    // ---- Cholesky S = L L^T (SPD: eigenvalues >= 1) ----
    float l00 = sqrtf(S00);                 float i0 = 1.0f / l00;
    float l10 = S01 * i0;
    float l20 = S02 * i0;
    float l30 = S03 * i0;
    float l11 = sqrtf(S11 - l10 * l10);     float i1 = 1.0f / l11;
    float l21 = (S12 - l20 * l10) * i1;
    float l31 = (S13 - l30 * l10) * i1;
    float l22 = sqrtf(S22 - l20 * l20 - l21 * l21); float i2 = 1.0f / l22;
    float l32 = (S23 - l30 * l20 - l31 * l21) * i2;
    float l33 = sqrtf(S33 - l30 * l30 - l31 * l31 - l32 * l32); float i3 = 1.0f / l33;

    // ---- K[8][4]: solve S K^T = PHT^T (fwd/back subst per row of PHT) ----
    float K[8][4];
    #pragma unroll
    for (int i = 0; i < 8; i++) {
        float b0 = PHT[i][0], b1 = PHT[i][1], b2 = PHT[i][2], b3 = PHT[i][3];
        float w0 = b0 * i0;
        float w1 = (b1 - l10 * w0) * i1;
        float w2 = (b2 - l20 * w0 - l21 * w1) * i2;
        float w3 = (b3 - l30 * w0 - l31 * w1 - l32 * w2) * i3;
        float k3 = w3 * i3;
        float k2 = (w2 - l32 * k3) * i2;
        float k1 = (w1 - l21 * k2 - l31 * k3) * i1;
        float k0 = (w0 - l10 * k1 - l20 * k2 - l30 * k3) * i0;
        K[i][0] = k0; K[i][1] = k1; K[i][2] = k2; K[i][3] = k3;
    }

    // ---- x_new = x + K y ----
    float xn[8];
    #pragma unroll
    for (int i = 0; i < 8; i++)
        xn[i] = xr[i] + K[i][0] * y0 + K[i][1] * y1 + K[i][2] * y2 + K[i][3] * y3;

    // ---- C = K * S  [8][4]  (S symmetric) ----
    float C[8][4];
    #pragma unroll
    for (int i = 0; i < 8; i++) {
        float k0 = K[i][0], k1 = K[i][1], k2 = K[i][2], k3 = K[i][3];
        C[i][0] = k0 * S00 + k1 * S01 + k2 * S02 + k3 * S03;
        C[i][1] = k0 * S01 + k1 * S11 + k2 * S12 + k3 * S13;
        C[i][2] = k0 * S02 + k1 * S12 + k2 * S22 + k3 * S23;
        C[i][3] = k0 * S03 + k1 * S13 + k2 * S23 + k3 * S33;
    }

    // ---- P_new = P - T - T^T + K S K^T, with T[i][j] = K[i].PHT[j]  ----
    // (Joseph form, using exact symmetry of input P; symmetric -> upper only)
    #pragma unroll
    for (int i = 0; i < 8; i++) {
        #pragma unroll
        for (int j = i; j < 8; j++) {
            float tij = K[i][0] * PHT[j][0] + K[i][1] * PHT[j][1]
                      + K[i][2] * PHT[j][2] + K[i][3] * PHT[j][3];
            float tji = K[j][0] * PHT[i][0] + K[j][1] * PHT[i][1]
                      + K[j][2] * PHT[i][2] + K[j][3] * PHT[i][3];
            float q   = C[i][0] * K[j][0] + C[i][1] * K[j][1]
                      + C[i][2] * K[j][2] + C[i][3] * K[j][3];
            float v = p[i][j] - tij - tji + q;
            p[i][j] = v;
            p[j][i] = v;
        }
    }

    // ---- Store: [x_new^T (8); P_new (8x8)] = 18 float4 ----
    float4* ob = out4 + (size_t)b * 18;
    ob[0] = make_float4(xn[0], xn[1], xn[2], xn[3]);
    ob[1] = make_float4(xn[4], xn[5], xn[6], xn[7]);
    #pragma unroll
    for (int i = 0; i < 8; i++) {
        ob[2 + 2 * i]     = make_float4(p[i][0], p[i][1], p[i][2], p[i][3]);
        ob[2 + 2 * i + 1] = make_float4(p[i][4], p[i][5], p[i][6], p[i][7]);
    }
}

extern "C" void kernel_launch(void* const* d_in, const int* in_sizes, int n_in,
                              void* d_out, int out_size) {
    const float4* x4 = (const float4*)d_in[0];
    const float4* z4 = (const float4*)d_in[1];
    const float4* P4 = (const float4*)d_in[2];
    const float*  Hg = (const float*)d_in[3];
    const float*  Rg = (const float*)d_in[4];
    float4* out4 = (float4*)d_out;

    int nb = in_sizes[0] / 8;  // B
    int grid = (nb + BT - 1) / BT;
    kalman_kernel<<<grid, BT>>>(x4, z4, P4, Hg, Rg, out4, nb);
}

// round 2
// speedup vs baseline: 1.2809x; 1.2809x over previous
#include <cuda_runtime.h>
#include <cuda_bf16.h>

// Batched Kalman update: B=262144, DX=8, DZ=4.
// Inputs: x [B,8,1] f32, z [B,4,1] f32, P [B,8,8] f32, H [4,8] f32, R [4,4] f32.
// Output: [B, 9, 8] f32 = concat(x_new^T, P_new).
//
// Strategy: one thread per batch, but ALL global traffic goes through a
// transposed shared-memory staging area so every LDG/STG is a fully
// coalesced float4 (128B/wavefront instead of 16B/wavefront).
// P never lives in registers: read on the fly from smem, overwritten
// in place with P_new.  Simplified exact update P_new = P - K*PHT^T
// (equal to Joseph form when K = PHT S^{-1} is the optimal gain).

#define NT 128        // threads per block
#define BPB 128       // batches per block (1 thread : 1 batch)
#define STR 129       // smem batch stride (odd -> conflict-free column reads)

__global__ void __launch_bounds__(NT, 4) kalman_kernel(
    const float4* __restrict__ x4,
    const float4* __restrict__ z4,
    const float4* __restrict__ P4,
    const float*  __restrict__ Hg,
    const float*  __restrict__ Rg,
    float4*       __restrict__ out4,
    int nb)
{
    __shared__ float Ps[64 * STR];   // [elem 0..63][batch]  ~33 KB
    __shared__ float xs[8 * STR];    // [elem 0..7][batch]
    __shared__ float Hs[32];
    __shared__ float Rs[16];

    const int t  = threadIdx.x;
    const int b0 = blockIdx.x * BPB;
    const int nbb = min(BPB, nb - b0);

    if (t < 32) Hs[t] = Hg[t];
    if (t < 16) Rs[t] = Rg[t];

    // ---- Stage P: coalesced float4 loads -> transposed smem ----
    {
        const int total = nbb * 16;              // float4 count
        #pragma unroll
        for (int k = 0; k < 16; k++) {
            int idx = t + NT * k;
            if (idx < total) {
                float4 v = P4[(size_t)b0 * 16 + idx];
                int m = idx >> 4;                // batch within block
                int e = (idx & 15) * 4;          // element start
                Ps[(e + 0) * STR + m] = v.x;
                Ps[(e + 1) * STR + m] = v.y;
                Ps[(e + 2) * STR + m] = v.z;
                Ps[(e + 3) * STR + m] = v.w;
            }
        }
    }
    // ---- Stage x: coalesced ----
    {
        const int total = nbb * 2;
        #pragma unroll
        for (int k = 0; k < 2; k++) {
            int idx = t + NT * k;
            if (idx < total) {
                float4 v = x4[(size_t)b0 * 2 + idx];
                int m = idx >> 1;
                int e = (idx & 1) * 4;
                xs[(e + 0) * STR + m] = v.x;
                xs[(e + 1) * STR + m] = v.y;
                xs[(e + 2) * STR + m] = v.z;
                xs[(e + 3) * STR + m] = v.w;
            }
        }
    }
    // ---- z is naturally coalesced: one float4 per batch ----
    float4 zz = make_float4(0.f, 0.f, 0.f, 0.f);
    if (t < nbb) zz = z4[b0 + t];

    __syncthreads();

    if (t < nbb) {
        float y0 = zz.x, y1 = zz.y, y2 = zz.z, y3 = zz.w;

        // ---- PHT = P H^T [8][4]; fold y = z - H x into same loop ----
        float PHT[8][4];
        #pragma unroll
        for (int i = 0; i < 8; i++)
            #pragma unroll
            for (int c = 0; c < 4; c++) PHT[i][c] = 0.f;

        #pragma unroll
        for (int k = 0; k < 8; k++) {
            float h0 = Hs[k], h1 = Hs[8 + k], h2 = Hs[16 + k], h3 = Hs[24 + k];
            float xk = xs[k * STR + t];
            y0 -= h0 * xk; y1 -= h1 * xk; y2 -= h2 * xk; y3 -= h3 * xk;
            #pragma unroll
            for (int i = 0; i < 8; i++) {
                float pik = Ps[(i * 8 + k) * STR + t];
                PHT[i][0] += pik * h0;
                PHT[i][1] += pik * h1;
                PHT[i][2] += pik * h2;
                PHT[i][3] += pik * h3;
            }
        }

        // ---- S = H * PHT + R (symmetric upper) ----
        float S00 = 0.f, S01 = 0.f, S02 = 0.f, S03 = 0.f;
        float S11 = 0.f, S12 = 0.f, S13 = 0.f;
        float S22 = 0.f, S23 = 0.f, S33 = 0.f;
        #pragma unroll
        for (int i = 0; i < 8; i++) {
            float h0 = Hs[i], h1 = Hs[8 + i], h2 = Hs[16 + i], h3 = Hs[24 + i];
            float q0 = PHT[i][0], q1 = PHT[i][1], q2 = PHT[i][2], q3 = PHT[i][3];
            S00 += h0 * q0; S01 += h0 * q1; S02 += h0 * q2; S03 += h0 * q3;
            S11 += h1 * q1; S12 += h1 * q2; S13 += h1 * q3;
            S22 += h2 * q2; S23 += h2 * q3;
            S33 += h3 * q3;
        }
        S00 += Rs[0];  S01 += Rs[1];  S02 += Rs[2];  S03 += Rs[3];
        S11 += Rs[5];  S12 += Rs[6];  S13 += Rs[7];
        S22 += Rs[10]; S23 += Rs[11]; S33 += Rs[15];

        // ---- Cholesky S = L L^T (SPD, eigenvalues >= 1) ----
        float l00 = sqrtf(S00);                  float i0 = 1.0f / l00;
        float l10 = S01 * i0;
        float l20 = S02 * i0;
        float l30 = S03 * i0;
        float l11 = sqrtf(S11 - l10 * l10);      float i1 = 1.0f / l11;
        float l21 = (S12 - l20 * l10) * i1;
        float l31 = (S13 - l30 * l10) * i1;
        float l22 = sqrtf(S22 - l20 * l20 - l21 * l21); float i2 = 1.0f / l22;
        float l32 = (S23 - l30 * l20 - l31 * l21) * i2;
        float l33 = sqrtf(S33 - l30 * l30 - l31 * l31 - l32 * l32); float i3 = 1.0f / l33;

        // ---- K[8][4]: solve S K^T = PHT^T row-wise ----
        float K[8][4];
        #pragma unroll
        for (int i = 0; i < 8; i++) {
            float w0 = PHT[i][0] * i0;
            float w1 = (PHT[i][1] - l10 * w0) * i1;
            float w2 = (PHT[i][2] - l20 * w0 - l21 * w1) * i2;
            float w3 = (PHT[i][3] - l30 * w0 - l31 * w1 - l32 * w2) * i3;
            float k3 = w3 * i3;
            float k2 = (w2 - l32 * k3) * i2;
            float k1 = (w1 - l21 * k2 - l31 * k3) * i1;
            float k0 = (w0 - l10 * k1 - l20 * k2 - l30 * k3) * i0;
            K[i][0] = k0; K[i][1] = k1; K[i][2] = k2; K[i][3] = k3;
        }

        // ---- x_new = x + K y  (stage into xs, overwriting x) ----
        float xn[8];
        #pragma unroll
        for (int i = 0; i < 8; i++)
            xn[i] = xs[i * STR + t]
                  + K[i][0] * y0 + K[i][1] * y1 + K[i][2] * y2 + K[i][3] * y3;
        #pragma unroll
        for (int i = 0; i < 8; i++)
            xs[i * STR + t] = xn[i];

        // ---- P_new = P - K * PHT^T  (== Joseph form for optimal K) ----
        // Read upper triangle from smem, write both halves back in place.
        #pragma unroll
        for (int i = 0; i < 8; i++) {
            #pragma unroll
            for (int j = i; j < 8; j++) {
                float pij = Ps[(i * 8 + j) * STR + t];
                float v = pij - (K[i][0] * PHT[j][0] + K[i][1] * PHT[j][1]
                               + K[i][2] * PHT[j][2] + K[i][3] * PHT[j][3]);
                Ps[(i * 8 + j) * STR + t] = v;
                if (j != i) Ps[(j * 8 + i) * STR + t] = v;
            }
        }
    }

    __syncthreads();

    // ---- Write out: coalesced float4 STG from staged smem ----
    // Output layout per batch: 72 floats = xn[0..7] ++ P_new[0..63]
    {
        const int total = nbb * 18;              // float4 count
        #pragma unroll
        for (int k = 0; k < 18; k++) {
            int idx = t + NT * k;
            if (idx < total) {
                int m  = idx / 18;
                int e0 = (idx % 18) * 4;         // 0,4,...,68
                float v0, v1, v2, v3;
                if (e0 < 8) {
                    v0 = xs[(e0 + 0) * STR + m];
                    v1 = xs[(e0 + 1) * STR + m];
                    v2 = xs[(e0 + 2) * STR + m];
                    v3 = xs[(e0 + 3) * STR + m];
                } else {
                    int e = e0 - 8;
                    v0 = Ps[(e + 0) * STR + m];
                    v1 = Ps[(e + 1) * STR + m];
                    v2 = Ps[(e + 2) * STR + m];
                    v3 = Ps[(e + 3) * STR + m];
                }
                out4[(size_t)b0 * 18 + idx] = make_float4(v0, v1, v2, v3);
            }
        }
    }
}

extern "C" void kernel_launch(void* const* d_in, const int* in_sizes, int n_in,
                              void* d_out, int out_size) {
    const float4* x4 = (const float4*)d_in[0];
    const float4* z4 = (const float4*)d_in[1];
    const float4* P4 = (const float4*)d_in[2];
    const float*  Hg = (const float*)d_in[3];
    const float*  Rg = (const float*)d_in[4];
    float4* out4 = (float4*)d_out;

    int nb = in_sizes[0] / 8;                    // B
    int grid = (nb + BPB - 1) / BPB;
    kalman_kernel<<<grid, NT>>>(x4, z4, P4, Hg, Rg, out4, nb);
}

// round 3
// speedup vs baseline: 1.4054x; 1.0973x over previous
#include <cuda_runtime.h>
#include <cuda_bf16.h>

// Batched Kalman update: B=262144, DX=8, DZ=4. One thread per batch.
//
// All global traffic is coalesced float4 through a [batch][elem] smem region
// of 19 float4 (76 floats) per batch: 19 is odd -> every 8-lane phase of an
// LDS.128/STS.128 hits distinct bank-quads (conflict-free), and the region
// layout [x(2q) | P(16q) | pad(1q)] is exactly the output record, so the
// drain phase is a direct copy.
//
// Math (W-form, identical to Joseph form for the optimal gain):
//   PHT = P H^T, S = H PHT + R = L L^T (SPD, eig >= 1)
//   W = PHT L^-T (forward substitution), u = L^-1 y
//   x_new = x + W u,  P_new = P - W W^T

#define NT  128
#define SREG 19   // float4 stride per batch region

__global__ void __launch_bounds__(NT, 4) kalman_kernel(
    const float4* __restrict__ x4,
    const float4* __restrict__ z4,
    const float4* __restrict__ P4,
    const float*  __restrict__ Hg,
    const float*  __restrict__ Rg,
    float4*       __restrict__ out4,
    int nb)
{
    __shared__ float4 Buf4[NT * SREG];   // 38912 B
    __shared__ float  Hs[32];
    __shared__ float  Rs[16];

    const int t   = threadIdx.x;
    const int b0  = blockIdx.x * NT;
    const int nbb = min(NT, nb - b0);

    if (t < 32) Hs[t] = Hg[t];
    if (t < 16) Rs[t] = Rg[t];

    // ---- Stage P: coalesced LDG.128 -> conflict-free STS.128 ----
    {
        const int total = nbb * 16;
        #pragma unroll
        for (int k = 0; k < 16; k++) {
            int idx = t + NT * k;
            if (idx < total) {
                int m = idx >> 4, f = idx & 15;
                Buf4[m * SREG + 2 + f] = P4[(size_t)b0 * 16 + idx];
            }
        }
    }
    // ---- Stage x ----
    {
        const int total = nbb * 2;
        #pragma unroll
        for (int k = 0; k < 2; k++) {
            int idx = t + NT * k;
            if (idx < total) {
                int m = idx >> 1, f = idx & 1;
                Buf4[m * SREG + f] = x4[(size_t)b0 * 2 + idx];
            }
        }
    }
    float4 zz = make_float4(0.f, 0.f, 0.f, 0.f);
    if (t < nbb) zz = z4[b0 + t];

    __syncthreads();

    if (t < nbb) {
        const int rb = t * SREG;

        // H rows into registers (broadcast LDS, hoisted once)
        float h0[8], h1[8], h2[8], h3[8];
        #pragma unroll
        for (int k = 0; k < 8; k++) {
            h0[k] = Hs[k]; h1[k] = Hs[8 + k]; h2[k] = Hs[16 + k]; h3[k] = Hs[24 + k];
        }

        // x, y = z - H x
        float4 xa = Buf4[rb], xb = Buf4[rb + 1];
        float xr[8] = { xa.x, xa.y, xa.z, xa.w, xb.x, xb.y, xb.z, xb.w };
        float y0 = zz.x, y1 = zz.y, y2 = zz.z, y3 = zz.w;
        #pragma unroll
        for (int k = 0; k < 8; k++) {
            y0 -= h0[k] * xr[k]; y1 -= h1[k] * xr[k];
            y2 -= h2[k] * xr[k]; y3 -= h3[k] * xr[k];
        }

        // PHT rows (stored in W, transformed in place later) + S accumulation
        float W[8][4];
        float S00 = 0.f, S01 = 0.f, S02 = 0.f, S03 = 0.f;
        float S11 = 0.f, S12 = 0.f, S13 = 0.f;
        float S22 = 0.f, S23 = 0.f, S33 = 0.f;
        #pragma unroll
        for (int i = 0; i < 8; i++) {
            float4 ra = Buf4[rb + 2 + 2 * i];
            float4 rc = Buf4[rb + 3 + 2 * i];
            float r[8] = { ra.x, ra.y, ra.z, ra.w, rc.x, rc.y, rc.z, rc.w };
            float q0 = 0.f, q1 = 0.f, q2 = 0.f, q3 = 0.f;
            #pragma unroll
            for (int k = 0; k < 8; k++) {
                q0 += r[k] * h0[k]; q1 += r[k] * h1[k];
                q2 += r[k] * h2[k]; q3 += r[k] * h3[k];
            }
            W[i][0] = q0; W[i][1] = q1; W[i][2] = q2; W[i][3] = q3;
            // S_{cd} += H[c][i] * q_d   (upper triangle)
            S00 += h0[i] * q0; S01 += h0[i] * q1; S02 += h0[i] * q2; S03 += h0[i] * q3;
            S11 += h1[i] * q1; S12 += h1[i] * q2; S13 += h1[i] * q3;
            S22 += h2[i] * q2; S23 += h2[i] * q3;
            S33 += h3[i] * q3;
        }
        S00 += Rs[0];  S01 += Rs[1];  S02 += Rs[2];  S03 += Rs[3];
        S11 += Rs[5];  S12 += Rs[6];  S13 += Rs[7];
        S22 += Rs[10]; S23 += Rs[11]; S33 += Rs[15];

        // Cholesky (only inverse diagonals + sub-diagonal factors needed)
        float i0 = rsqrtf(S00);
        float l10 = S01 * i0, l20 = S02 * i0, l30 = S03 * i0;
        float d1 = S11 - l10 * l10;
        float i1 = rsqrtf(d1);
        float l21 = (S12 - l20 * l10) * i1;
        float l31 = (S13 - l30 * l10) * i1;
        float d2 = S22 - l20 * l20 - l21 * l21;
        float i2 = rsqrtf(d2);
        float l32 = (S23 - l30 * l20 - l31 * l21) * i2;
        float d3 = S33 - l30 * l30 - l31 * l31 - l32 * l32;
        float i3 = rsqrtf(d3);

        // W = PHT L^-T  (forward substitution, in place)
        #pragma unroll
        for (int i = 0; i < 8; i++) {
            float w0 = W[i][0] * i0;
            float w1 = (W[i][1] - l10 * w0) * i1;
            float w2 = (W[i][2] - l20 * w0 - l21 * w1) * i2;
            float w3 = (W[i][3] - l30 * w0 - l31 * w1 - l32 * w2) * i3;
            W[i][0] = w0; W[i][1] = w1; W[i][2] = w2; W[i][3] = w3;
        }

        // u = L^-1 y
        float u0 = y0 * i0;
        float u1 = (y1 - l10 * u0) * i1;
        float u2 = (y2 - l20 * u0 - l21 * u1) * i2;
        float u3 = (y3 - l30 * u0 - l31 * u1 - l32 * u2) * i3;

        // x_new = x + W u  -> overwrite x quads in region
        float xn[8];
        #pragma unroll
        for (int i = 0; i < 8; i++)
            xn[i] = xr[i] + W[i][0] * u0 + W[i][1] * u1 + W[i][2] * u2 + W[i][3] * u3;
        Buf4[rb]     = make_float4(xn[0], xn[1], xn[2], xn[3]);
        Buf4[rb + 1] = make_float4(xn[4], xn[5], xn[6], xn[7]);

        // P_new = P - W W^T  (row-wise, in place, vector smem ops only)
        #pragma unroll
        for (int i = 0; i < 8; i++) {
            float4 pa = Buf4[rb + 2 + 2 * i];
            float4 pc = Buf4[rb + 3 + 2 * i];
            float pr[8] = { pa.x, pa.y, pa.z, pa.w, pc.x, pc.y, pc.z, pc.w };
            float w0 = W[i][0], w1 = W[i][1], w2 = W[i][2], w3 = W[i][3];
            float o[8];
            #pragma unroll
            for (int j = 0; j < 8; j++)
                o[j] = pr[j] - (w0 * W[j][0] + w1 * W[j][1] + w2 * W[j][2] + w3 * W[j][3]);
            Buf4[rb + 2 + 2 * i] = make_float4(o[0], o[1], o[2], o[3]);
            Buf4[rb + 3 + 2 * i] = make_float4(o[4], o[5], o[6], o[7]);
        }
    }

    __syncthreads();

    // ---- Drain: region quads 0..17 are exactly the output record ----
    {
        const int total = nbb * 18;
        #pragma unroll
        for (int k = 0; k < 18; k++) {
            int idx = t + NT * k;
            if (idx < total) {
                int m = idx / 18;
                int j = idx - m * 18;
                out4[(size_t)b0 * 18 + idx] = Buf4[m * SREG + j];
            }
        }
    }
}

extern "C" void kernel_launch(void* const* d_in, const int* in_sizes, int n_in,
                              void* d_out, int out_size) {
    const float4* x4 = (const float4*)d_in[0];
    const float4* z4 = (const float4*)d_in[1];
    const float4* P4 = (const float4*)d_in[2];
    const float*  Hg = (const float*)d_in[3];
    const float*  Rg = (const float*)d_in[4];
    float4* out4 = (float4*)d_out;

    int nb = in_sizes[0] / 8;            // B
    int grid = (nb + NT - 1) / NT;
    kalman_kernel<<<grid, NT>>>(x4, z4, P4, Hg, Rg, out4, nb);
}

// round 4
// speedup vs baseline: 1.6388x; 1.1661x over previous
#include <cuda_runtime.h>
#include <cuda_bf16.h>

// Batched Kalman update: B=262144, DX=8, DZ=4.  TWO threads per batch.
// Pair = lanes (2m, 2m+1); comms via __shfl_xor(.,1). Thread h owns rows
// 4h..4h+3 of P/W, processed in rotated order so simultaneous pair smem
// accesses differ by 4 quads mod 8 (conflict-free with SREG=19).
//
// Math (W-form == Joseph form for the optimal gain):
//   PHT = P H^T, S = H PHT + R = L L^T;  W = PHT L^-T,  u = L^-1 y
//   x_new = x + W u,  P_new = P - W W^T

#define NT   128
#define BPB  64          // batches per block (2 threads per batch)
#define SREG 19          // float4 region stride per batch

__global__ void __launch_bounds__(NT, 7) kalman_kernel(
    const float4* __restrict__ x4,
    const float4* __restrict__ z4,
    const float4* __restrict__ P4,
    const float*  __restrict__ Hg,
    const float*  __restrict__ Rg,
    float4*       __restrict__ out4,
    int nb)
{
    __shared__ float4 Buf4[BPB * SREG];   // 19456 B: [x(2q) | P(16q) | z(1q)]
    __shared__ float4 HT4[8];             // HT4[k] = (H[0][k],H[1][k],H[2][k],H[3][k])
    __shared__ float  Rs[16];

    const int t   = threadIdx.x;
    const int b0  = blockIdx.x * BPB;
    const int nbb = min(BPB, nb - b0);

    if (t < 8)  HT4[t] = make_float4(Hg[t], Hg[8 + t], Hg[16 + t], Hg[24 + t]);
    if (t >= 32 && t < 48) Rs[t - 32] = Rg[t - 32];

    // ---- Stage P (coalesced LDG.128 -> consecutive-quad STS.128) ----
    {
        const int total = nbb * 16;
        #pragma unroll
        for (int k = 0; k < 8; k++) {
            int idx = t + NT * k;
            if (idx < total) {
                int m = idx >> 4, f = idx & 15;
                Buf4[m * SREG + 2 + f] = P4[(size_t)b0 * 16 + idx];
            }
        }
    }
    // ---- Stage x ----
    {
        int idx = t;
        if (idx < nbb * 2) {
            int m = idx >> 1, f = idx & 1;
            Buf4[m * SREG + f] = x4[(size_t)b0 * 2 + idx];
        }
    }
    // ---- Stage z into the pad quad ----
    if (t < nbb) Buf4[t * SREG + 18] = z4[b0 + t];

    __syncthreads();

    if (t < 2 * nbb) {
        const int m  = t >> 1;
        const int h  = t & 1;          // which half of the rows this thread owns
        const int rb = m * SREG;
        const unsigned FM = 0xffffffffu;

        // own row for iteration i:  h=0 -> 0,1,2,3 ; h=1 -> 6,7,4,5
        // (rotation keeps pair smem accesses 4 quads apart mod 8)
        int rown[4];
        #pragma unroll
        for (int i = 0; i < 4; i++) rown[i] = 4 * h + ((i + 2 * h) & 3);

        // ---- y = z - H x  (pair-partial) ----
        float4 xq = Buf4[rb + h];
        float  xo[4] = { xq.x, xq.y, xq.z, xq.w };
        float4 zq = Buf4[rb + 18];
        float s0 = 0.f, s1 = 0.f, s2 = 0.f, s3 = 0.f;
        #pragma unroll
        for (int kk = 0; kk < 4; kk++) {
            float4 ht = HT4[4 * h + kk];
            s0 += ht.x * xo[kk]; s1 += ht.y * xo[kk];
            s2 += ht.z * xo[kk]; s3 += ht.w * xo[kk];
        }
        float y0 = zq.x - (s0 + __shfl_xor_sync(FM, s0, 1));
        float y1 = zq.y - (s1 + __shfl_xor_sync(FM, s1, 1));
        float y2 = zq.z - (s2 + __shfl_xor_sync(FM, s2, 1));
        float y3 = zq.w - (s3 + __shfl_xor_sync(FM, s3, 1));

        // ---- PHT rows (own 4) -> W, plus partial S ----
        float pr[4][8];
        #pragma unroll
        for (int i = 0; i < 4; i++) {
            float4 pa = Buf4[rb + 2 + 2 * rown[i]];
            float4 pb = Buf4[rb + 3 + 2 * rown[i]];
            pr[i][0] = pa.x; pr[i][1] = pa.y; pr[i][2] = pa.z; pr[i][3] = pa.w;
            pr[i][4] = pb.x; pr[i][5] = pb.y; pr[i][6] = pb.z; pr[i][7] = pb.w;
        }
        float W[4][4] = {};
        #pragma unroll
        for (int k = 0; k < 8; k++) {
            float4 ht = HT4[k];
            #pragma unroll
            for (int i = 0; i < 4; i++) {
                W[i][0] += pr[i][k] * ht.x; W[i][1] += pr[i][k] * ht.y;
                W[i][2] += pr[i][k] * ht.z; W[i][3] += pr[i][k] * ht.w;
            }
        }

        float S00 = 0.f, S01 = 0.f, S02 = 0.f, S03 = 0.f;
        float S11 = 0.f, S12 = 0.f, S13 = 0.f;
        float S22 = 0.f, S23 = 0.f, S33 = 0.f;
        #pragma unroll
        for (int i = 0; i < 4; i++) {
            float4 ht = HT4[rown[i]];     // H[:, row]
            float q0 = W[i][0], q1 = W[i][1], q2 = W[i][2], q3 = W[i][3];
            S00 += ht.x * q0; S01 += ht.x * q1; S02 += ht.x * q2; S03 += ht.x * q3;
            S11 += ht.y * q1; S12 += ht.y * q2; S13 += ht.y * q3;
            S22 += ht.z * q2; S23 += ht.z * q3;
            S33 += ht.w * q3;
        }
        S00 += __shfl_xor_sync(FM, S00, 1); S01 += __shfl_xor_sync(FM, S01, 1);
        S02 += __shfl_xor_sync(FM, S02, 1); S03 += __shfl_xor_sync(FM, S03, 1);
        S11 += __shfl_xor_sync(FM, S11, 1); S12 += __shfl_xor_sync(FM, S12, 1);
        S13 += __shfl_xor_sync(FM, S13, 1); S22 += __shfl_xor_sync(FM, S22, 1);
        S23 += __shfl_xor_sync(FM, S23, 1); S33 += __shfl_xor_sync(FM, S33, 1);
        S00 += Rs[0];  S01 += Rs[1];  S02 += Rs[2];  S03 += Rs[3];
        S11 += Rs[5];  S12 += Rs[6];  S13 += Rs[7];
        S22 += Rs[10]; S23 += Rs[11]; S33 += Rs[15];

        // ---- Cholesky (redundant per pair — cheap) ----
        float i0  = rsqrtf(S00);
        float l10 = S01 * i0, l20 = S02 * i0, l30 = S03 * i0;
        float i1  = rsqrtf(S11 - l10 * l10);
        float l21 = (S12 - l20 * l10) * i1;
        float l31 = (S13 - l30 * l10) * i1;
        float i2  = rsqrtf(S22 - l20 * l20 - l21 * l21);
        float l32 = (S23 - l30 * l20 - l31 * l21) * i2;
        float i3  = rsqrtf(S33 - l30 * l30 - l31 * l31 - l32 * l32);

        // ---- W = PHT L^-T (own rows) ----
        #pragma unroll
        for (int i = 0; i < 4; i++) {
            float w0 = W[i][0] * i0;
            float w1 = (W[i][1] - l10 * w0) * i1;
            float w2 = (W[i][2] - l20 * w0 - l21 * w1) * i2;
            float w3 = (W[i][3] - l30 * w0 - l31 * w1 - l32 * w2) * i3;
            W[i][0] = w0; W[i][1] = w1; W[i][2] = w2; W[i][3] = w3;
        }

        // ---- u = L^-1 y ----
        float u0 = y0 * i0;
        float u1 = (y1 - l10 * u0) * i1;
        float u2 = (y2 - l20 * u0 - l21 * u1) * i2;
        float u3 = (y3 - l30 * u0 - l31 * u1 - l32 * u2) * i3;

        // ---- exchange W with partner ----
        float pW[4][4];
        #pragma unroll
        for (int s = 0; s < 4; s++)
            #pragma unroll
            for (int c = 0; c < 4; c++)
                pW[s][c] = __shfl_xor_sync(FM, W[s][c], 1);

        // global-row-indexed W:  rows 0..3 in WA, rows 4..7 in WB
        // owner(j<4)=h0 slot j ; owner(j>=4)=h1 slot (j-2)&3
        float WA[4][4], WB[4][4];
        #pragma unroll
        for (int j = 0; j < 4; j++)
            #pragma unroll
            for (int c = 0; c < 4; c++) {
                WA[j][c] = h ? pW[j][c] : W[j][c];
                int s = (j + 2) & 3;
                WB[j][c] = h ? W[s][c] : pW[s][c];
            }

        // ---- x_new own quad: element 4h+kk uses own W slot (kk+2h)&3 ----
        {
            float xn[4];
            #pragma unroll
            for (int kk = 0; kk < 4; kk++) {
                float w0, w1, w2, w3;
                int sa = kk, sb = (kk + 2) & 3;
                w0 = h ? W[sb][0] : W[sa][0];
                w1 = h ? W[sb][1] : W[sa][1];
                w2 = h ? W[sb][2] : W[sa][2];
                w3 = h ? W[sb][3] : W[sa][3];
                xn[kk] = xo[kk] + w0 * u0 + w1 * u1 + w2 * u2 + w3 * u3;
            }
            Buf4[rb + h] = make_float4(xn[0], xn[1], xn[2], xn[3]);
        }

        // ---- P_new own rows: P - W W^T ----
        #pragma unroll
        for (int i = 0; i < 4; i++) {
            int r = rown[i];
            float4 pa = Buf4[rb + 2 + 2 * r];
            float4 pb = Buf4[rb + 3 + 2 * r];
            float prow[8] = { pa.x, pa.y, pa.z, pa.w, pb.x, pb.y, pb.z, pb.w };
            float w0 = W[i][0], w1 = W[i][1], w2 = W[i][2], w3 = W[i][3];
            float o[8];
            #pragma unroll
            for (int j = 0; j < 4; j++)
                o[j] = prow[j] - (w0 * WA[j][0] + w1 * WA[j][1]
                                + w2 * WA[j][2] + w3 * WA[j][3]);
            #pragma unroll
            for (int j = 0; j < 4; j++)
                o[4 + j] = prow[4 + j] - (w0 * WB[j][0] + w1 * WB[j][1]
                                        + w2 * WB[j][2] + w3 * WB[j][3]);
            Buf4[rb + 2 + 2 * r] = make_float4(o[0], o[1], o[2], o[3]);
            Buf4[rb + 3 + 2 * r] = make_float4(o[4], o[5], o[6], o[7]);
        }
    }

    __syncthreads();

    // ---- Drain: quads 0..17 of each region are exactly the output record ----
    {
        const int total = nbb * 18;
        #pragma unroll
        for (int k = 0; k < 9; k++) {
            int idx = t + NT * k;
            if (idx < total) {
                int mm = idx / 18;
                int j  = idx - mm * 18;
                out4[(size_t)b0 * 18 + idx] = Buf4[mm * SREG + j];
            }
        }
    }
}

extern "C" void kernel_launch(void* const* d_in, const int* in_sizes, int n_in,
                              void* d_out, int out_size) {
    const float4* x4 = (const float4*)d_in[0];
    const float4* z4 = (const float4*)d_in[1];
    const float4* P4 = (const float4*)d_in[2];
    const float*  Hg = (const float*)d_in[3];
    const float*  Rg = (const float*)d_in[4];
    float4* out4 = (float4*)d_out;

    int nb = in_sizes[0] / 8;            // B
    int grid = (nb + BPB - 1) / BPB;
    kalman_kernel<<<grid, NT>>>(x4, z4, P4, Hg, Rg, out4, nb);
}

// round 5
// speedup vs baseline: 1.7233x; 1.0515x over previous
#include <cuda_runtime.h>
#include <cuda_bf16.h>

// Batched Kalman update: B=262144, DX=8, DZ=4.  TWO threads per batch.
// Pair = lanes (2m, 2m+1). Thread h owns rows rown = h0:{0,1,2,3}, h1:{6,7,4,5}
// (rotation keeps simultaneous pair smem accesses on distinct bank-quads).
//
// W-form math (== Joseph form for the optimal gain):
//   PHT = P H^T, S = H PHT + R = L L^T;  W = PHT L^-T,  u = L^-1 y
//   x_new = x + W u,  P_new = P - W W^T
//
// Epilogue fetches global W rows via absolute-lane shfl (no WA/WB registers).

#define NT   128
#define BPB  64
#define SREG 19

__global__ void __launch_bounds__(NT, 8) kalman_kernel(
    const float4* __restrict__ x4,
    const float4* __restrict__ z4,
    const float4* __restrict__ P4,
    const float*  __restrict__ Hg,
    const float*  __restrict__ Rg,
    float4*       __restrict__ out4,
    int nb)
{
    __shared__ float4 Buf4[BPB * SREG];   // [x(2q) | P(16q) | z(1q)] per batch
    __shared__ float4 HT4[8];             // HT4[k] = H[0..3][k]
    __shared__ float  Rs[16];

    const int t   = threadIdx.x;
    const int b0  = blockIdx.x * BPB;
    const int nbb = min(BPB, nb - b0);

    if (t < 8)  HT4[t] = make_float4(Hg[t], Hg[8 + t], Hg[16 + t], Hg[24 + t]);
    if (t >= 32 && t < 48) Rs[t - 32] = Rg[t - 32];

    // ---- Stage P (coalesced LDG.128 -> STS.128) ----
    {
        const int total = nbb * 16;
        #pragma unroll
        for (int k = 0; k < 8; k++) {
            int idx = t + NT * k;
            if (idx < total) {
                int m = idx >> 4, f = idx & 15;
                Buf4[m * SREG + 2 + f] = P4[(size_t)b0 * 16 + idx];
            }
        }
    }
    // ---- Stage x ----
    if (t < nbb * 2) {
        int m = t >> 1, f = t & 1;
        Buf4[m * SREG + f] = x4[(size_t)b0 * 2 + t];
    }
    // ---- Stage z ----
    if (t < nbb) Buf4[t * SREG + 18] = z4[b0 + t];

    __syncthreads();

    if (t < 2 * nbb) {
        const int m  = t >> 1;
        const int h  = t & 1;
        const int rb = m * SREG;
        const unsigned FM = 0xffffffffu;

        int rown[4];
        #pragma unroll
        for (int i = 0; i < 4; i++) rown[i] = 4 * h + ((i + 2 * h) & 3);

        // ---- y = z - H x (pair-partial) ----
        float4 xq = Buf4[rb + h];
        float xo0 = xq.x, xo1 = xq.y, xo2 = xq.z, xo3 = xq.w;
        float4 zq = Buf4[rb + 18];
        float s0, s1, s2, s3;
        {
            float4 ha = HT4[4 * h + 0], hb = HT4[4 * h + 1];
            float4 hc = HT4[4 * h + 2], hd = HT4[4 * h + 3];
            s0 = ha.x * xo0 + hb.x * xo1 + hc.x * xo2 + hd.x * xo3;
            s1 = ha.y * xo0 + hb.y * xo1 + hc.y * xo2 + hd.y * xo3;
            s2 = ha.z * xo0 + hb.z * xo1 + hc.z * xo2 + hd.z * xo3;
            s3 = ha.w * xo0 + hb.w * xo1 + hc.w * xo2 + hd.w * xo3;
        }
        float y0 = zq.x - (s0 + __shfl_xor_sync(FM, s0, 1));
        float y1 = zq.y - (s1 + __shfl_xor_sync(FM, s1, 1));
        float y2 = zq.z - (s2 + __shfl_xor_sync(FM, s2, 1));
        float y3 = zq.w - (s3 + __shfl_xor_sync(FM, s3, 1));

        // ---- W = PHT rows (own 4, row-wise to keep registers low) ----
        float W[4][4];
        #pragma unroll
        for (int i = 0; i < 4; i++) {
            int r = rown[i];
            float4 pa = Buf4[rb + 2 + 2 * r];
            float4 pb = Buf4[rb + 3 + 2 * r];
            float q0, q1, q2, q3;
            {
                float4 h0q = HT4[0], h1q = HT4[1], h2q = HT4[2], h3q = HT4[3];
                q0 = pa.x * h0q.x + pa.y * h1q.x + pa.z * h2q.x + pa.w * h3q.x;
                q1 = pa.x * h0q.y + pa.y * h1q.y + pa.z * h2q.y + pa.w * h3q.y;
                q2 = pa.x * h0q.z + pa.y * h1q.z + pa.z * h2q.z + pa.w * h3q.z;
                q3 = pa.x * h0q.w + pa.y * h1q.w + pa.z * h2q.w + pa.w * h3q.w;
            }
            {
                float4 h4q = HT4[4], h5q = HT4[5], h6q = HT4[6], h7q = HT4[7];
                q0 += pb.x * h4q.x + pb.y * h5q.x + pb.z * h6q.x + pb.w * h7q.x;
                q1 += pb.x * h4q.y + pb.y * h5q.y + pb.z * h6q.y + pb.w * h7q.y;
                q2 += pb.x * h4q.z + pb.y * h5q.z + pb.z * h6q.z + pb.w * h7q.z;
                q3 += pb.x * h4q.w + pb.y * h5q.w + pb.z * h6q.w + pb.w * h7q.w;
            }
            W[i][0] = q0; W[i][1] = q1; W[i][2] = q2; W[i][3] = q3;
        }

        // ---- S partial from own rows, then pair-reduce ----
        float S00 = 0.f, S01 = 0.f, S02 = 0.f, S03 = 0.f;
        float S11 = 0.f, S12 = 0.f, S13 = 0.f;
        float S22 = 0.f, S23 = 0.f, S33 = 0.f;
        #pragma unroll
        for (int i = 0; i < 4; i++) {
            float4 ht = HT4[rown[i]];
            float q0 = W[i][0], q1 = W[i][1], q2 = W[i][2], q3 = W[i][3];
            S00 += ht.x * q0; S01 += ht.x * q1; S02 += ht.x * q2; S03 += ht.x * q3;
            S11 += ht.y * q1; S12 += ht.y * q2; S13 += ht.y * q3;
            S22 += ht.z * q2; S23 += ht.z * q3;
            S33 += ht.w * q3;
        }
        S00 += __shfl_xor_sync(FM, S00, 1); S01 += __shfl_xor_sync(FM, S01, 1);
        S02 += __shfl_xor_sync(FM, S02, 1); S03 += __shfl_xor_sync(FM, S03, 1);
        S11 += __shfl_xor_sync(FM, S11, 1); S12 += __shfl_xor_sync(FM, S12, 1);
        S13 += __shfl_xor_sync(FM, S13, 1); S22 += __shfl_xor_sync(FM, S22, 1);
        S23 += __shfl_xor_sync(FM, S23, 1); S33 += __shfl_xor_sync(FM, S33, 1);
        S00 += Rs[0];  S01 += Rs[1];  S02 += Rs[2];  S03 += Rs[3];
        S11 += Rs[5];  S12 += Rs[6];  S13 += Rs[7];
        S22 += Rs[10]; S23 += Rs[11]; S33 += Rs[15];

        // ---- Cholesky ----
        float i0  = rsqrtf(S00);
        float l10 = S01 * i0, l20 = S02 * i0, l30 = S03 * i0;
        float i1  = rsqrtf(S11 - l10 * l10);
        float l21 = (S12 - l20 * l10) * i1;
        float l31 = (S13 - l30 * l10) * i1;
        float i2  = rsqrtf(S22 - l20 * l20 - l21 * l21);
        float l32 = (S23 - l30 * l20 - l31 * l21) * i2;
        float i3  = rsqrtf(S33 - l30 * l30 - l31 * l31 - l32 * l32);

        // ---- W <- W L^-T ----
        #pragma unroll
        for (int i = 0; i < 4; i++) {
            float w0 = W[i][0] * i0;
            float w1 = (W[i][1] - l10 * w0) * i1;
            float w2 = (W[i][2] - l20 * w0 - l21 * w1) * i2;
            float w3 = (W[i][3] - l30 * w0 - l31 * w1 - l32 * w2) * i3;
            W[i][0] = w0; W[i][1] = w1; W[i][2] = w2; W[i][3] = w3;
        }

        // ---- u = L^-1 y ----
        float u0 = y0 * i0;
        float u1 = (y1 - l10 * u0) * i1;
        float u2 = (y2 - l20 * u0 - l21 * u1) * i2;
        float u3 = (y3 - l30 * u0 - l31 * u1 - l32 * u2) * i3;

        // ---- x_new own quad ----
        {
            float v0 = W[0][0] * u0 + W[0][1] * u1 + W[0][2] * u2 + W[0][3] * u3;
            float v1 = W[1][0] * u0 + W[1][1] * u1 + W[1][2] * u2 + W[1][3] * u3;
            float v2 = W[2][0] * u0 + W[2][1] * u1 + W[2][2] * u2 + W[2][3] * u3;
            float v3 = W[3][0] * u0 + W[3][1] * u1 + W[3][2] * u2 + W[3][3] * u3;
            // element order: h0 slots map 0,1,2,3 ; h1 slots map to elems 2,3,0,1
            float e0 = h ? v2 : v0, e1 = h ? v3 : v1;
            float e2 = h ? v0 : v2, e3 = h ? v1 : v3;
            Buf4[rb + h] = make_float4(xo0 + e0, xo1 + e1, xo2 + e2, xo3 + e3);
        }

        // ---- P_new = P - W W^T  (own rows; global W rows via absolute shfl) ----
        float po[4][8];
        #pragma unroll
        for (int i = 0; i < 4; i++) {
            int r = rown[i];
            float4 pa = Buf4[rb + 2 + 2 * r];
            float4 pb = Buf4[rb + 3 + 2 * r];
            po[i][0] = pa.x; po[i][1] = pa.y; po[i][2] = pa.z; po[i][3] = pa.w;
            po[i][4] = pb.x; po[i][5] = pb.y; po[i][6] = pb.z; po[i][7] = pb.w;
        }
        const int lane2 = (t & 31) & ~1;     // even lane of this pair
        #pragma unroll
        for (int g = 0; g < 8; g++) {
            const int src  = lane2 | (g >> 2);              // owner lane of row g
            const int slot = (g < 4) ? g : ((g + 2) & 3);   // owner's W slot
            float wg0 = __shfl_sync(FM, W[slot][0], src);
            float wg1 = __shfl_sync(FM, W[slot][1], src);
            float wg2 = __shfl_sync(FM, W[slot][2], src);
            float wg3 = __shfl_sync(FM, W[slot][3], src);
            #pragma unroll
            for (int i = 0; i < 4; i++)
                po[i][g] -= W[i][0] * wg0 + W[i][1] * wg1
                          + W[i][2] * wg2 + W[i][3] * wg3;
        }
        #pragma unroll
        for (int i = 0; i < 4; i++) {
            int r = rown[i];
            Buf4[rb + 2 + 2 * r] = make_float4(po[i][0], po[i][1], po[i][2], po[i][3]);
            Buf4[rb + 3 + 2 * r] = make_float4(po[i][4], po[i][5], po[i][6], po[i][7]);
        }
    }

    __syncthreads();

    // ---- Drain: quads 0..17 of each region are exactly the output record ----
    {
        const int total = nbb * 18;
        #pragma unroll
        for (int k = 0; k < 9; k++) {
            int idx = t + NT * k;
            if (idx < total) {
                int mm = idx / 18;
                int j  = idx - mm * 18;
                out4[(size_t)b0 * 18 + idx] = Buf4[mm * SREG + j];
            }
        }
    }
}

extern "C" void kernel_launch(void* const* d_in, const int* in_sizes, int n_in,
                              void* d_out, int out_size) {
    const float4* x4 = (const float4*)d_in[0];
    const float4* z4 = (const float4*)d_in[1];
    const float4* P4 = (const float4*)d_in[2];
    const float*  Hg = (const float*)d_in[3];
    const float*  Rg = (const float*)d_in[4];
    float4* out4 = (float4*)d_out;

    int nb = in_sizes[0] / 8;            // B
    int grid = (nb + BPB - 1) / BPB;
    kalman_kernel<<<grid, NT>>>(x4, z4, P4, Hg, Rg, out4, nb);
}